// round 1
// baseline (speedup 1.0000x reference)
#include <cuda_runtime.h>
#include <math_constants.h>

#define CCH   512
#define HH    64
#define WW    64
#define FX    7
#define FY    7
#define BINS  (FX*FY)            // 49
#define SEG   (CCH*BINS)         // 25088
#define DTOT  (SEG*6)            // 150528
#define NOUT  1024
#define KCHUNK 512
#define NCHUNKS (DTOT/KCHUNK)    // 294  (512 divides 25088: 25088/512 = 49)

// Scratch (no allocation allowed in kernel_launch)
__device__ float g_pools[16 * SEG];            // 16 pools, each [C, FX, FY] channel-major
__device__ float g_partial[NCHUNKS * 3 * NOUT];

// ---------------------------------------------------------------------------
// Pool kernel: one block per channel. Loads the 64x64 plane into SMEM once,
// computes all 16 pools x 49 bins for that channel.
// Pool index map: 0 = scene, 1..3 = human[i], 4..15 = obj-union(i,j) (i*4+j).
// ---------------------------------------------------------------------------
__global__ void __launch_bounds__(256) pool_kernel(
    const float* __restrict__ feature,
    const float* __restrict__ pbox,   // [3,4] x1,y1,x2,y2 (image coords)
    const float* __restrict__ obox,   // [4,4]
    const float* __restrict__ ratio)  // [2]
{
    __shared__ float plane[HH * WW];
    __shared__ int bx0[16], by0[16], bx1[16], by1[16];

    const int ch  = blockIdx.x;
    const int tid = threadIdx.x;

    if (tid < 16) {
        const float rx = ratio[0], ry = ratio[1];
        int p = tid;
        int x0, y0, x1, y1;
        if (p == 0) {
            x0 = 0; y0 = 0; x1 = WW; y1 = HH;
        } else if (p < 4) {
            int i = p - 1;
            x0 = (int)rintf(pbox[i*4+0] * rx);
            y0 = (int)rintf(pbox[i*4+1] * ry);
            x1 = (int)rintf(pbox[i*4+2] * rx);
            y1 = (int)rintf(pbox[i*4+3] * ry);
        } else {
            int q = p - 4; int i = q >> 2; int j = q & 3;
            int px0 = (int)rintf(pbox[i*4+0] * rx);
            int py0 = (int)rintf(pbox[i*4+1] * ry);
            int px1 = (int)rintf(pbox[i*4+2] * rx);
            int py1 = (int)rintf(pbox[i*4+3] * ry);
            int ox0 = (int)rintf(obox[j*4+0] * rx);
            int oy0 = (int)rintf(obox[j*4+1] * ry);
            int ox1 = (int)rintf(obox[j*4+2] * rx);
            int oy1 = (int)rintf(obox[j*4+3] * ry);
            x0 = min(px0, ox0); y0 = min(py0, oy0);
            x1 = max(px1, ox1); y1 = max(py1, oy1);
        }
        bx0[p] = x0; by0[p] = y0; bx1[p] = x1; by1[p] = y1;
    }

    // Coalesced plane load (1024 float4)
    {
        const float4* src = (const float4*)(feature + (size_t)ch * (HH * WW));
        float4* dst = (float4*)plane;
        #pragma unroll
        for (int idx = tid; idx < (HH * WW) / 4; idx += 256)
            dst[idx] = src[idx];
    }
    __syncthreads();

    // 784 bin tasks over 256 threads
    for (int task = tid; task < 16 * BINS; task += 256) {
        int p   = task / BINS;
        int bin = task - p * BINS;
        int i = bin / FY, j = bin - i * FY;
        int x0 = bx0[p], y0 = by0[p];
        int h = by1[p] - y0;
        int w = bx1[p] - x0;
        // PyTorch adaptive bins: start = floor(i*h/F), end = ceil((i+1)*h/F)
        int rs = y0 + (i * h) / FX;
        int re = y0 + ((i + 1) * h + FX - 1) / FX;
        int cs = x0 + (j * w) / FY;
        int ce = x0 + ((j + 1) * w + FY - 1) / FY;
        float m = -CUDART_INF_F;
        for (int r = rs; r < re; r++) {
            const float* row = plane + r * WW;
            for (int c = cs; c < ce; c++)
                m = fmaxf(m, row[c]);
        }
        g_pools[p * SEG + ch * BINS + bin] = m;
    }
}

// ---------------------------------------------------------------------------
// Split-K GEMM: out[m,n] = sum_d act[m,d] * W[d,n]
// act row m = concat(human[m], obj[4m..4m+3], scene); each 512-row K-chunk
// lies entirely in one concat segment, so activations are 3 base pointers
// into g_pools. One block = all 1024 N columns (256 thr x float4), one chunk.
// ---------------------------------------------------------------------------
__global__ void __launch_bounds__(256) gemm_kernel(const float* __restrict__ Wf)
{
    const int chunk  = blockIdx.x;
    const int k0     = chunk * KCHUNK;
    const int seg    = k0 / SEG;            // 0..5
    const int within = k0 - seg * SEG;

    int p0, p1, p2;
    if (seg == 0)      { p0 = 1;       p1 = 2;       p2 = 3;       } // human[m]
    else if (seg == 5) { p0 = 0;       p1 = 0;       p2 = 0;       } // scene
    else               { p0 = 3 + seg; p1 = 7 + seg; p2 = 11 + seg; } // obj[4m+seg-1]

    const float* __restrict__ a0 = g_pools + p0 * SEG + within;
    const float* __restrict__ a1 = g_pools + p1 * SEG + within;
    const float* __restrict__ a2 = g_pools + p2 * SEG + within;

    const int n = threadIdx.x * 4;
    const float* wp = Wf + (size_t)k0 * NOUT + n;

    float4 s0 = make_float4(0.f, 0.f, 0.f, 0.f);
    float4 s1 = s0, s2 = s0;

    #pragma unroll 4
    for (int d = 0; d < KCHUNK; d++) {
        float4 w4 = *(const float4*)wp;
        wp += NOUT;
        float x0 = __ldg(a0 + d);
        float x1 = __ldg(a1 + d);
        float x2 = __ldg(a2 + d);
        s0.x = fmaf(x0, w4.x, s0.x); s0.y = fmaf(x0, w4.y, s0.y);
        s0.z = fmaf(x0, w4.z, s0.z); s0.w = fmaf(x0, w4.w, s0.w);
        s1.x = fmaf(x1, w4.x, s1.x); s1.y = fmaf(x1, w4.y, s1.y);
        s1.z = fmaf(x1, w4.z, s1.z); s1.w = fmaf(x1, w4.w, s1.w);
        s2.x = fmaf(x2, w4.x, s2.x); s2.y = fmaf(x2, w4.y, s2.y);
        s2.z = fmaf(x2, w4.z, s2.z); s2.w = fmaf(x2, w4.w, s2.w);
    }

    float* outp = g_partial + (size_t)chunk * 3 * NOUT;
    *(float4*)(outp + n)            = s0;
    *(float4*)(outp + NOUT + n)     = s1;
    *(float4*)(outp + 2 * NOUT + n) = s2;
}

// ---------------------------------------------------------------------------
// Deterministic reduce over the 294 K-chunks + bias.
// ---------------------------------------------------------------------------
__global__ void __launch_bounds__(256) reduce_kernel(
    const float* __restrict__ bias, float* __restrict__ out)
{
    int i = blockIdx.x * 256 + threadIdx.x;   // 0..3071
    if (i >= 3 * NOUT) return;
    int n = i & (NOUT - 1);
    float s = bias[n];
    #pragma unroll 7
    for (int c = 0; c < NCHUNKS; c++)
        s += g_partial[(size_t)c * 3 * NOUT + i];
    out[i] = s;
}

extern "C" void kernel_launch(void* const* d_in, const int* in_sizes, int n_in,
                              void* d_out, int out_size)
{
    const float* feature = (const float*)d_in[0];
    const float* pbox    = (const float*)d_in[1];
    const float* obox    = (const float*)d_in[2];
    const float* ratio   = (const float*)d_in[3];
    const float* Wf      = (const float*)d_in[4];
    const float* bias    = (const float*)d_in[5];
    float* out = (float*)d_out;

    pool_kernel<<<CCH, 256>>>(feature, pbox, obox, ratio);
    gemm_kernel<<<NCHUNKS, 256>>>(Wf);
    reduce_kernel<<<(3 * NOUT + 255) / 256, 256>>>(bias, out);
}

// round 4
// speedup vs baseline: 1.7920x; 1.7920x over previous
#include <cuda_runtime.h>
#include <math_constants.h>

#define CCH   512
#define HH    64
#define WW    64
#define FX    7
#define FY    7
#define BINS  (FX*FY)            // 49
#define SEG   (CCH*BINS)         // 25088
#define DTOT  (SEG*6)            // 150528
#define NOUT  1024
#define KCHUNK 256
#define NCHUNKS (DTOT/KCHUNK)    // 588

// Scratch (no allocation allowed in kernel_launch)
__device__ float g_pools[16 * SEG];              // 16 pools, each [C, FX, FY] channel-major
__device__ float g_partial[NCHUNKS * 3 * NOUT];  // 7.2 MB

// ---------------------------------------------------------------------------
// Pool kernel: one block per channel. Loads the 64x64 plane into SMEM once,
// computes all 16 pools x 49 bins for that channel.
// Pool index map: 0 = scene, 1..3 = human[i], 4..15 = obj-union(i,j) (i*4+j).
// ---------------------------------------------------------------------------
__global__ void __launch_bounds__(256) pool_kernel(
    const float* __restrict__ feature,
    const float* __restrict__ pbox,   // [3,4] x1,y1,x2,y2 (image coords)
    const float* __restrict__ obox,   // [4,4]
    const float* __restrict__ ratio)  // [2]
{
    __shared__ float plane[HH * WW];
    __shared__ int bx0[16], by0[16], bx1[16], by1[16];

    const int ch  = blockIdx.x;
    const int tid = threadIdx.x;

    if (tid < 16) {
        const float rx = ratio[0], ry = ratio[1];
        int p = tid;
        int x0, y0, x1, y1;
        if (p == 0) {
            x0 = 0; y0 = 0; x1 = WW; y1 = HH;
        } else if (p < 4) {
            int i = p - 1;
            x0 = (int)rintf(pbox[i*4+0] * rx);
            y0 = (int)rintf(pbox[i*4+1] * ry);
            x1 = (int)rintf(pbox[i*4+2] * rx);
            y1 = (int)rintf(pbox[i*4+3] * ry);
        } else {
            int q = p - 4; int i = q >> 2; int j = q & 3;
            int px0 = (int)rintf(pbox[i*4+0] * rx);
            int py0 = (int)rintf(pbox[i*4+1] * ry);
            int px1 = (int)rintf(pbox[i*4+2] * rx);
            int py1 = (int)rintf(pbox[i*4+3] * ry);
            int ox0 = (int)rintf(obox[j*4+0] * rx);
            int oy0 = (int)rintf(obox[j*4+1] * ry);
            int ox1 = (int)rintf(obox[j*4+2] * rx);
            int oy1 = (int)rintf(obox[j*4+3] * ry);
            x0 = min(px0, ox0); y0 = min(py0, oy0);
            x1 = max(px1, ox1); y1 = max(py1, oy1);
        }
        bx0[p] = x0; by0[p] = y0; bx1[p] = x1; by1[p] = y1;
    }

    // Coalesced plane load (1024 float4)
    {
        const float4* src = (const float4*)(feature + (size_t)ch * (HH * WW));
        float4* dst = (float4*)plane;
        #pragma unroll
        for (int idx = tid; idx < (HH * WW) / 4; idx += 256)
            dst[idx] = src[idx];
    }
    __syncthreads();

    // 784 bin tasks over 256 threads
    for (int task = tid; task < 16 * BINS; task += 256) {
        int p   = task / BINS;
        int bin = task - p * BINS;
        int i = bin / FY, j = bin - i * FY;
        int x0 = bx0[p], y0 = by0[p];
        int h = by1[p] - y0;
        int w = bx1[p] - x0;
        // PyTorch adaptive bins: start = floor(i*h/F), end = ceil((i+1)*h/F)
        int rs = y0 + (i * h) / FX;
        int re = y0 + ((i + 1) * h + FX - 1) / FX;
        int cs = x0 + (j * w) / FY;
        int ce = x0 + ((j + 1) * w + FY - 1) / FY;
        float m = -CUDART_INF_F;
        for (int r = rs; r < re; r++) {
            const float* row = plane + r * WW;
            for (int c = cs; c < ce; c++)
                m = fmaxf(m, row[c]);
        }
        g_pools[p * SEG + ch * BINS + bin] = m;
    }
}

// ---------------------------------------------------------------------------
// Split-K GEMM: out[m,n] = sum_d act[m,d] * W[d,n]
// act row m = concat(human[m], obj[4m..4m+3], scene); each 256-row K-chunk
// lies entirely in one concat segment (256 divides 25088), so activations
// are 3 base pointers into g_pools, staged in SMEM.
// One block = all 1024 N columns (256 thr x float4), one K-chunk of 256.
// ---------------------------------------------------------------------------
__global__ void __launch_bounds__(256, 4) gemm_kernel(const float* __restrict__ Wf)
{
    __shared__ float sa0[KCHUNK], sa1[KCHUNK], sa2[KCHUNK];

    const int chunk  = blockIdx.x;
    const int k0     = chunk * KCHUNK;
    const int seg    = k0 / SEG;            // 0..5
    const int within = k0 - seg * SEG;

    int p0, p1, p2;
    if (seg == 0)      { p0 = 1;       p1 = 2;       p2 = 3;       } // human[m]
    else if (seg == 5) { p0 = 0;       p1 = 0;       p2 = 0;       } // scene
    else               { p0 = 3 + seg; p1 = 7 + seg; p2 = 11 + seg; } // obj[4m+seg-1]

    const int tid = threadIdx.x;
    sa0[tid] = g_pools[p0 * SEG + within + tid];
    sa1[tid] = g_pools[p1 * SEG + within + tid];
    sa2[tid] = g_pools[p2 * SEG + within + tid];
    __syncthreads();

    const int n = tid * 4;
    const float* wp = Wf + (size_t)k0 * NOUT + n;

    float4 s0 = make_float4(0.f, 0.f, 0.f, 0.f);
    float4 s1 = s0, s2 = s0;

    for (int d = 0; d < KCHUNK; d += 8) {
        float4 w[8];
        #pragma unroll
        for (int u = 0; u < 8; u++)
            w[u] = __ldcs((const float4*)(wp + (size_t)u * NOUT));
        wp += 8 * NOUT;
        #pragma unroll
        for (int u = 0; u < 8; u++) {
            float x0 = sa0[d + u];
            float x1 = sa1[d + u];
            float x2 = sa2[d + u];
            s0.x = fmaf(x0, w[u].x, s0.x); s0.y = fmaf(x0, w[u].y, s0.y);
            s0.z = fmaf(x0, w[u].z, s0.z); s0.w = fmaf(x0, w[u].w, s0.w);
            s1.x = fmaf(x1, w[u].x, s1.x); s1.y = fmaf(x1, w[u].y, s1.y);
            s1.z = fmaf(x1, w[u].z, s1.z); s1.w = fmaf(x1, w[u].w, s1.w);
            s2.x = fmaf(x2, w[u].x, s2.x); s2.y = fmaf(x2, w[u].y, s2.y);
            s2.z = fmaf(x2, w[u].z, s2.z); s2.w = fmaf(x2, w[u].w, s2.w);
        }
    }

    float* outp = g_partial + (size_t)chunk * 3 * NOUT;
    *(float4*)(outp + n)            = s0;
    *(float4*)(outp + NOUT + n)     = s1;
    *(float4*)(outp + 2 * NOUT + n) = s2;
}

// ---------------------------------------------------------------------------
// Deterministic reduce over the K-chunks + bias.
// ---------------------------------------------------------------------------
__global__ void __launch_bounds__(256) reduce_kernel(
    const float* __restrict__ bias, float* __restrict__ out)
{
    int i = blockIdx.x * 256 + threadIdx.x;   // 0..3071
    if (i >= 3 * NOUT) return;
    int n = i & (NOUT - 1);
    float s = bias[n];
    #pragma unroll 4
    for (int c = 0; c < NCHUNKS; c++)
        s += g_partial[(size_t)c * 3 * NOUT + i];
    out[i] = s;
}

extern "C" void kernel_launch(void* const* d_in, const int* in_sizes, int n_in,
                              void* d_out, int out_size)
{
    const float* feature = (const float*)d_in[0];
    const float* pbox    = (const float*)d_in[1];
    const float* obox    = (const float*)d_in[2];
    const float* ratio   = (const float*)d_in[3];
    const float* Wf      = (const float*)d_in[4];
    const float* bias    = (const float*)d_in[5];
    float* out = (float*)d_out;

    pool_kernel<<<CCH, 256>>>(feature, pbox, obox, ratio);
    gemm_kernel<<<NCHUNKS, 256>>>(Wf);
    reduce_kernel<<<(3 * NOUT + 255) / 256, 256>>>(bias, out);
}

// round 5
// speedup vs baseline: 2.3291x; 1.2997x over previous
#include <cuda_runtime.h>
#include <math_constants.h>

#define CCH   512
#define HH    64
#define WW    64
#define FX    7
#define FY    7
#define BINS  (FX*FY)            // 49
#define SEG   (CCH*BINS)         // 25088
#define DTOT  (SEG*6)            // 150528
#define NOUT  1024
#define KCHUNK 256
#define NCHUNKS (DTOT/KCHUNK)    // 588

// Scratch (no allocation allowed in kernel_launch)
__device__ float g_pools[16 * SEG];              // 16 pools, each [C, FX, FY] channel-major
__device__ float g_partial[NCHUNKS * 3 * NOUT];  // 7.2 MB

// ---------------------------------------------------------------------------
// Pool kernel: one block per (channel, group of 4 pools). Loads the 64x64
// plane into SMEM, computes its 4 pools x 49 bins.
// Pool index map: 0 = scene, 1..3 = human[i], 4..15 = obj-union(i,j) (i*4+j).
// ---------------------------------------------------------------------------
__global__ void __launch_bounds__(256) pool_kernel(
    const float* __restrict__ feature,
    const float* __restrict__ pbox,   // [3,4] x1,y1,x2,y2 (image coords)
    const float* __restrict__ obox,   // [4,4]
    const float* __restrict__ ratio)  // [2]
{
    __shared__ float plane[HH * WW];
    __shared__ int bx0[16], by0[16], bx1[16], by1[16];

    const int ch  = blockIdx.x;
    const int pg  = blockIdx.y * 4;      // first pool of this block's group
    const int tid = threadIdx.x;

    if (tid < 16) {
        const float rx = ratio[0], ry = ratio[1];
        int p = tid;
        int x0, y0, x1, y1;
        if (p == 0) {
            x0 = 0; y0 = 0; x1 = WW; y1 = HH;
        } else if (p < 4) {
            int i = p - 1;
            x0 = (int)rintf(pbox[i*4+0] * rx);
            y0 = (int)rintf(pbox[i*4+1] * ry);
            x1 = (int)rintf(pbox[i*4+2] * rx);
            y1 = (int)rintf(pbox[i*4+3] * ry);
        } else {
            int q = p - 4; int i = q >> 2; int j = q & 3;
            int px0 = (int)rintf(pbox[i*4+0] * rx);
            int py0 = (int)rintf(pbox[i*4+1] * ry);
            int px1 = (int)rintf(pbox[i*4+2] * rx);
            int py1 = (int)rintf(pbox[i*4+3] * ry);
            int ox0 = (int)rintf(obox[j*4+0] * rx);
            int oy0 = (int)rintf(obox[j*4+1] * ry);
            int ox1 = (int)rintf(obox[j*4+2] * rx);
            int oy1 = (int)rintf(obox[j*4+3] * ry);
            x0 = min(px0, ox0); y0 = min(py0, oy0);
            x1 = max(px1, ox1); y1 = max(py1, oy1);
        }
        bx0[p] = x0; by0[p] = y0; bx1[p] = x1; by1[p] = y1;
    }

    // Coalesced plane load (1024 float4)
    {
        const float4* src = (const float4*)(feature + (size_t)ch * (HH * WW));
        float4* dst = (float4*)plane;
        #pragma unroll
        for (int idx = tid; idx < (HH * WW) / 4; idx += 256)
            dst[idx] = src[idx];
    }
    __syncthreads();

    // 196 bin tasks (4 pools x 49 bins) over 256 threads
    for (int task = tid; task < 4 * BINS; task += 256) {
        int p   = pg + task / BINS;
        int bin = task % BINS;
        int i = bin / FY, j = bin - i * FY;
        int x0 = bx0[p], y0 = by0[p];
        int h = by1[p] - y0;
        int w = bx1[p] - x0;
        // PyTorch adaptive bins: start = floor(i*h/F), end = ceil((i+1)*h/F)
        int rs = y0 + (i * h) / FX;
        int re = y0 + ((i + 1) * h + FX - 1) / FX;
        int cs = x0 + (j * w) / FY;
        int ce = x0 + ((j + 1) * w + FY - 1) / FY;
        float m = -CUDART_INF_F;
        for (int r = rs; r < re; r++) {
            const float* row = plane + r * WW;
            for (int c = cs; c < ce; c++)
                m = fmaxf(m, row[c]);
        }
        g_pools[p * SEG + ch * BINS + bin] = m;
    }
}

// ---------------------------------------------------------------------------
// Split-K GEMM: out[m,n] = sum_d act[m,d] * W[d,n]
// act row m = concat(human[m], obj[4m..4m+3], scene); each 256-row K-chunk
// lies entirely in one concat segment (256 divides 25088), so activations
// are 3 base pointers into g_pools, staged in SMEM.
// One block = all 1024 N columns (256 thr x float4), one K-chunk of 256.
// ---------------------------------------------------------------------------
__global__ void __launch_bounds__(256, 4) gemm_kernel(const float* __restrict__ Wf)
{
    __shared__ float sa0[KCHUNK], sa1[KCHUNK], sa2[KCHUNK];

    const int chunk  = blockIdx.x;
    const int k0     = chunk * KCHUNK;
    const int seg    = k0 / SEG;            // 0..5
    const int within = k0 - seg * SEG;

    int p0, p1, p2;
    if (seg == 0)      { p0 = 1;       p1 = 2;       p2 = 3;       } // human[m]
    else if (seg == 5) { p0 = 0;       p1 = 0;       p2 = 0;       } // scene
    else               { p0 = 3 + seg; p1 = 7 + seg; p2 = 11 + seg; } // obj[4m+seg-1]

    const int tid = threadIdx.x;
    sa0[tid] = g_pools[p0 * SEG + within + tid];
    sa1[tid] = g_pools[p1 * SEG + within + tid];
    sa2[tid] = g_pools[p2 * SEG + within + tid];
    __syncthreads();

    const int n = tid * 4;
    const float* wp = Wf + (size_t)k0 * NOUT + n;

    float4 s0 = make_float4(0.f, 0.f, 0.f, 0.f);
    float4 s1 = s0, s2 = s0;

    for (int d = 0; d < KCHUNK; d += 8) {
        float4 w[8];
        #pragma unroll
        for (int u = 0; u < 8; u++)
            w[u] = __ldcs((const float4*)(wp + (size_t)u * NOUT));
        wp += 8 * NOUT;
        #pragma unroll
        for (int u = 0; u < 8; u++) {
            float x0 = sa0[d + u];
            float x1 = sa1[d + u];
            float x2 = sa2[d + u];
            s0.x = fmaf(x0, w[u].x, s0.x); s0.y = fmaf(x0, w[u].y, s0.y);
            s0.z = fmaf(x0, w[u].z, s0.z); s0.w = fmaf(x0, w[u].w, s0.w);
            s1.x = fmaf(x1, w[u].x, s1.x); s1.y = fmaf(x1, w[u].y, s1.y);
            s1.z = fmaf(x1, w[u].z, s1.z); s1.w = fmaf(x1, w[u].w, s1.w);
            s2.x = fmaf(x2, w[u].x, s2.x); s2.y = fmaf(x2, w[u].y, s2.y);
            s2.z = fmaf(x2, w[u].z, s2.z); s2.w = fmaf(x2, w[u].w, s2.w);
        }
    }

    float* outp = g_partial + (size_t)chunk * 3 * NOUT;
    *(float4*)(outp + n)            = s0;
    *(float4*)(outp + NOUT + n)     = s1;
    *(float4*)(outp + 2 * NOUT + n) = s2;
}

// ---------------------------------------------------------------------------
// Deterministic reduce over the K-chunks + bias.
// 48 blocks x 256 threads: each block covers 64 outputs x 4 partial-slices
// (147 chunks each), then combines the 4 slices through SMEM.
// ---------------------------------------------------------------------------
__global__ void __launch_bounds__(256) reduce_kernel(
    const float* __restrict__ bias, float* __restrict__ out)
{
    __shared__ float red[256];
    const int tid  = threadIdx.x;
    const int i    = blockIdx.x * 64 + (tid & 63);   // output index 0..3071
    const int part = tid >> 6;                        // 0..3

    float s = 0.f;
    const float* src = g_partial + (size_t)(part * 147) * (3 * NOUT) + i;
    #pragma unroll 7
    for (int c = 0; c < 147; c++)
        s += src[(size_t)c * (3 * NOUT)];

    red[tid] = s;
    __syncthreads();

    if (tid < 64) {
        float t = red[tid] + red[tid + 64] + red[tid + 128] + red[tid + 192];
        out[i] = t + bias[i & (NOUT - 1)];
    }
}

extern "C" void kernel_launch(void* const* d_in, const int* in_sizes, int n_in,
                              void* d_out, int out_size)
{
    const float* feature = (const float*)d_in[0];
    const float* pbox    = (const float*)d_in[1];
    const float* obox    = (const float*)d_in[2];
    const float* ratio   = (const float*)d_in[3];
    const float* Wf      = (const float*)d_in[4];
    const float* bias    = (const float*)d_in[5];
    float* out = (float*)d_out;

    dim3 pgrid(CCH, 4);
    pool_kernel<<<pgrid, 256>>>(feature, pbox, obox, ratio);
    gemm_kernel<<<NCHUNKS, 256>>>(Wf);
    reduce_kernel<<<48, 256>>>(bias, out);
}

// round 6
// speedup vs baseline: 2.3651x; 1.0155x over previous
#include <cuda_runtime.h>
#include <math_constants.h>

#define CCH   512
#define HH    64
#define WW    64
#define FX    7
#define FY    7
#define BINS  (FX*FY)            // 49
#define SEG   (CCH*BINS)         // 25088
#define DTOT  (SEG*6)            // 150528
#define NOUT  1024
#define KCHUNK 256
#define NCHUNKS (DTOT/KCHUNK)    // 588

// Scratch (no allocation allowed in kernel_launch)
__device__ float g_pools[16 * SEG];              // 16 pools, each [C, FX, FY] channel-major
__device__ float g_partial[NCHUNKS * 3 * NOUT];  // 7.2 MB

// ---------------------------------------------------------------------------
// Pool kernel: one block per channel. Separable 2-pass adaptive max pool:
//   pass 1: strip[p][i][x] = max over rows of bin-row i of pool p, column x
//   pass 2: bin[p][i][j]   = max over column range of strip
// Cuts the dependent fmaxf chain from ~100 to ~10 and exposes 7168-way
// parallelism in pass 1 (vs 784 single-chain tasks).
// Pool index map: 0 = scene, 1..3 = human[i], 4..15 = obj-union(i,j) (i*4+j).
// ---------------------------------------------------------------------------
__global__ void __launch_bounds__(256) pool_kernel(
    const float* __restrict__ feature,
    const float* __restrict__ pbox,   // [3,4] x1,y1,x2,y2 (image coords)
    const float* __restrict__ obox,   // [4,4]
    const float* __restrict__ ratio)  // [2]
{
    __shared__ float plane[HH * WW];          // 16 KB
    __shared__ float strip[16 * FX * WW];     // 28 KB  [p][i][x]
    __shared__ int bx0[16], by0[16], bx1[16], by1[16];

    const int ch  = blockIdx.x;
    const int tid = threadIdx.x;

    if (tid < 16) {
        const float rx = ratio[0], ry = ratio[1];
        int p = tid;
        int x0, y0, x1, y1;
        if (p == 0) {
            x0 = 0; y0 = 0; x1 = WW; y1 = HH;
        } else if (p < 4) {
            int i = p - 1;
            x0 = (int)rintf(pbox[i*4+0] * rx);
            y0 = (int)rintf(pbox[i*4+1] * ry);
            x1 = (int)rintf(pbox[i*4+2] * rx);
            y1 = (int)rintf(pbox[i*4+3] * ry);
        } else {
            int q = p - 4; int i = q >> 2; int j = q & 3;
            int px0 = (int)rintf(pbox[i*4+0] * rx);
            int py0 = (int)rintf(pbox[i*4+1] * ry);
            int px1 = (int)rintf(pbox[i*4+2] * rx);
            int py1 = (int)rintf(pbox[i*4+3] * ry);
            int ox0 = (int)rintf(obox[j*4+0] * rx);
            int oy0 = (int)rintf(obox[j*4+1] * ry);
            int ox1 = (int)rintf(obox[j*4+2] * rx);
            int oy1 = (int)rintf(obox[j*4+3] * ry);
            x0 = min(px0, ox0); y0 = min(py0, oy0);
            x1 = max(px1, ox1); y1 = max(py1, oy1);
        }
        bx0[p] = x0; by0[p] = y0; bx1[p] = x1; by1[p] = y1;
    }

    // Coalesced plane load (1024 float4)
    {
        const float4* src = (const float4*)(feature + (size_t)ch * (HH * WW));
        float4* dst = (float4*)plane;
        #pragma unroll
        for (int idx = tid; idx < (HH * WW) / 4; idx += 256)
            dst[idx] = src[idx];
    }
    __syncthreads();

    // Pass 1: 112 (pool,striprow) pairs x 64 columns; 4 column-groups of 64
    // threads each. Lanes map to x -> conflict-free LDS. Uniform bounds
    // within each group (same (p,i) across its 2 warps).
    {
        const int xg = tid >> 6;    // 0..3
        const int x  = tid & 63;
        for (int t = xg; t < 16 * FX; t += 4) {
            int p = t / FX, i = t - p * FX;
            int y0 = by0[p];
            int h  = by1[p] - y0;
            int rs = y0 + (i * h) / FX;
            int re = y0 + ((i + 1) * h + FX - 1) / FX;
            float m = -CUDART_INF_F;
            for (int r = rs; r < re; r++)
                m = fmaxf(m, plane[r * WW + x]);
            strip[t * WW + x] = m;
        }
    }
    __syncthreads();

    // Pass 2: 784 bins over 256 threads (~3 each), chain ~10
    for (int t = tid; t < 16 * BINS; t += 256) {
        int p   = t / BINS;
        int bin = t - p * BINS;
        int i = bin / FY, j = bin - i * FY;
        int x0 = bx0[p];
        int w  = bx1[p] - x0;
        int cs = x0 + (j * w) / FY;
        int ce = x0 + ((j + 1) * w + FY - 1) / FY;
        const float* s = strip + (p * FX + i) * WW;
        float m = -CUDART_INF_F;
        for (int c = cs; c < ce; c++)
            m = fmaxf(m, s[c]);
        g_pools[p * SEG + ch * BINS + bin] = m;
    }
}

// ---------------------------------------------------------------------------
// Split-K GEMM: out[m,n] = sum_d act[m,d] * W[d,n]
// act row m = concat(human[m], obj[4m..4m+3], scene); each 256-row K-chunk
// lies entirely in one concat segment (256 divides 25088), so activations
// are 3 base pointers into g_pools, staged in SMEM.
// One block = all 1024 N columns (256 thr x float4), one K-chunk of 256.
// ---------------------------------------------------------------------------
__global__ void __launch_bounds__(256, 4) gemm_kernel(const float* __restrict__ Wf)
{
    __shared__ float sa0[KCHUNK], sa1[KCHUNK], sa2[KCHUNK];

    const int chunk  = blockIdx.x;
    const int k0     = chunk * KCHUNK;
    const int seg    = k0 / SEG;            // 0..5
    const int within = k0 - seg * SEG;

    int p0, p1, p2;
    if (seg == 0)      { p0 = 1;       p1 = 2;       p2 = 3;       } // human[m]
    else if (seg == 5) { p0 = 0;       p1 = 0;       p2 = 0;       } // scene
    else               { p0 = 3 + seg; p1 = 7 + seg; p2 = 11 + seg; } // obj[4m+seg-1]

    const int tid = threadIdx.x;
    sa0[tid] = g_pools[p0 * SEG + within + tid];
    sa1[tid] = g_pools[p1 * SEG + within + tid];
    sa2[tid] = g_pools[p2 * SEG + within + tid];
    __syncthreads();

    const int n = tid * 4;
    const float* wp = Wf + (size_t)k0 * NOUT + n;

    float4 s0 = make_float4(0.f, 0.f, 0.f, 0.f);
    float4 s1 = s0, s2 = s0;

    for (int d = 0; d < KCHUNK; d += 8) {
        float4 w[8];
        #pragma unroll
        for (int u = 0; u < 8; u++)
            w[u] = __ldcs((const float4*)(wp + (size_t)u * NOUT));
        wp += 8 * NOUT;
        #pragma unroll
        for (int u = 0; u < 8; u++) {
            float x0 = sa0[d + u];
            float x1 = sa1[d + u];
            float x2 = sa2[d + u];
            s0.x = fmaf(x0, w[u].x, s0.x); s0.y = fmaf(x0, w[u].y, s0.y);
            s0.z = fmaf(x0, w[u].z, s0.z); s0.w = fmaf(x0, w[u].w, s0.w);
            s1.x = fmaf(x1, w[u].x, s1.x); s1.y = fmaf(x1, w[u].y, s1.y);
            s1.z = fmaf(x1, w[u].z, s1.z); s1.w = fmaf(x1, w[u].w, s1.w);
            s2.x = fmaf(x2, w[u].x, s2.x); s2.y = fmaf(x2, w[u].y, s2.y);
            s2.z = fmaf(x2, w[u].z, s2.z); s2.w = fmaf(x2, w[u].w, s2.w);
        }
    }

    float* outp = g_partial + (size_t)chunk * 3 * NOUT;
    *(float4*)(outp + n)            = s0;
    *(float4*)(outp + NOUT + n)     = s1;
    *(float4*)(outp + 2 * NOUT + n) = s2;
}

// ---------------------------------------------------------------------------
// Deterministic reduce over the K-chunks + bias.
// 48 blocks x 256 threads: each block covers 64 outputs x 4 partial-slices
// (147 chunks each), then combines the 4 slices through SMEM.
// ---------------------------------------------------------------------------
__global__ void __launch_bounds__(256) reduce_kernel(
    const float* __restrict__ bias, float* __restrict__ out)
{
    __shared__ float red[256];
    const int tid  = threadIdx.x;
    const int i    = blockIdx.x * 64 + (tid & 63);   // output index 0..3071
    const int part = tid >> 6;                        // 0..3

    float s = 0.f;
    const float* src = g_partial + (size_t)(part * 147) * (3 * NOUT) + i;
    #pragma unroll 7
    for (int c = 0; c < 147; c++)
        s += src[(size_t)c * (3 * NOUT)];

    red[tid] = s;
    __syncthreads();

    if (tid < 64) {
        float t = red[tid] + red[tid + 64] + red[tid + 128] + red[tid + 192];
        out[i] = t + bias[i & (NOUT - 1)];
    }
}

extern "C" void kernel_launch(void* const* d_in, const int* in_sizes, int n_in,
                              void* d_out, int out_size)
{
    const float* feature = (const float*)d_in[0];
    const float* pbox    = (const float*)d_in[1];
    const float* obox    = (const float*)d_in[2];
    const float* ratio   = (const float*)d_in[3];
    const float* Wf      = (const float*)d_in[4];
    const float* bias    = (const float*)d_in[5];
    float* out = (float*)d_out;

    pool_kernel<<<CCH, 256>>>(feature, pbox, obox, ratio);
    gemm_kernel<<<NCHUNKS, 256>>>(Wf);
    reduce_kernel<<<48, 256>>>(bias, out);
}